// round 2
// baseline (speedup 1.0000x reference)
#include <cuda_runtime.h>
#include <cuda_bf16.h>
#include <math.h>

#define NN    8192
#define DIM   64
#define TOPK  64
#define BI    64      // i-rows per block (kernel 2)
#define TJ    128     // j-tile width
#define CAP   128     // max kept (sim>=0.5) entries per row
#define NT    256

// hn buffer (scratch): 8192 x 64 fp32 = 2MB, static device global (no allocs allowed)
__device__ float g_hn[NN * DIM];

// ---------------------------------------------------------------------------
// Kernel 1: hn = normalize(tanh(3*(emb[idx] @ W^T + b)));  also zero H.
// grid 2048 x 256: each block handles 4 rows (64 threads per row), and the
// 2048*256 = 524288 threads exactly zero the 64*8192 output.
// NOTE: idx is int32 on device (JAX default x64-disabled downcasts int64).
// ---------------------------------------------------------------------------
__global__ void __launch_bounds__(256) hn_kernel(
    const int* __restrict__ idx,
    const float* __restrict__ emb,
    const float* __restrict__ W,
    const float* __restrict__ bias,
    float* __restrict__ H)
{
    __shared__ float Ws[64 * 65];   // W padded: row d at Ws[d*65 + k]
    __shared__ float xs[4][64];
    __shared__ float red[4][2];

    int t = threadIdx.x;

    // zero output H (exact cover: 2048*256 == 64*8192)
    H[blockIdx.x * 256 + t] = 0.0f;

    // cooperative load of W into padded shared
    {
        int r  = t >> 2;
        int c0 = (t & 3) * 16;
        const float4* src = (const float4*)(W + r * 64 + c0);
        #pragma unroll
        for (int q = 0; q < 4; q++) {
            float4 v = src[q];
            int c = c0 + q * 4;
            Ws[r * 65 + c + 0] = v.x;
            Ws[r * 65 + c + 1] = v.y;
            Ws[r * 65 + c + 2] = v.z;
            Ws[r * 65 + c + 3] = v.w;
        }
    }

    int g   = t >> 6;        // row group 0..3
    int d   = t & 63;        // output dim
    int row = blockIdx.x * 4 + g;

    int src_row = idx[row] & (NN - 1);   // mask: degrade to wrong-answer, not crash
    xs[g][d] = emb[src_row * DIM + d];
    __syncthreads();

    float s = bias[d];
    #pragma unroll
    for (int k = 0; k < 64; k++)
        s += xs[g][k] * Ws[d * 65 + k];

    float h  = tanhf(3.0f * s);
    float sq = h * h;
    #pragma unroll
    for (int o = 16; o; o >>= 1)
        sq += __shfl_xor_sync(0xffffffffu, sq, o);
    int wig = (t >> 5) & 1;            // which warp of the 64-thread group
    if ((t & 31) == 0) red[g][wig] = sq;
    __syncthreads();

    float nrm = sqrtf(red[g][0] + red[g][1]);
    nrm = fmaxf(nrm, 1e-8f);
    g_hn[row * DIM + d] = h / nrm;
}

// ---------------------------------------------------------------------------
// Kernel 2: fused sim = hn@hn^T, threshold >= 0.5, collect survivors per row,
// exact top-64 with JAX stable tie-break, scatter into H[k, j].
// grid 128 x 256, ~114KB dynamic smem, one block per 64 rows.
// ---------------------------------------------------------------------------
extern __shared__ float smem2[];

__global__ void __launch_bounds__(256) sim_topk_kernel(float* __restrict__ H)
{
    const float* __restrict__ hn = g_hn;

    float* As    = smem2;                       // [64][68]  A^T: As[k][i]
    float* Bs    = As + 64 * 68;                // [64][132] B^T: Bs[k][j]
    float* keptV = Bs + 64 * 132;               // [BI*CAP]
    int*   keptJ = (int*)(keptV + BI * CAP);    // [BI*CAP]
    int*   cnt   = keptJ + BI * CAP;            // [BI]

    int t  = threadIdx.x;
    int ib = blockIdx.x * BI;

    if (t < BI) cnt[t] = 0;

    // load A tile (64 rows) transposed into As[k][i]
    {
        int i  = t >> 2;
        int d0 = (t & 3) * 16;
        const float4* src = (const float4*)(hn + (ib + i) * DIM + d0);
        #pragma unroll
        for (int q = 0; q < 4; q++) {
            float4 v = src[q];
            int d = d0 + q * 4;
            As[(d + 0) * 68 + i] = v.x;
            As[(d + 1) * 68 + i] = v.y;
            As[(d + 2) * 68 + i] = v.z;
            As[(d + 3) * 68 + i] = v.w;
        }
    }
    __syncthreads();

    int jg = t & 31;          // j micro-group: 4 columns
    int ig = t >> 5;          // i micro-group: 8 rows (== warp id)
    int j0 = jg * 4;
    int i0 = ig * 8;

    for (int jt = 0; jt < NN; jt += TJ) {
        // load B tile (128 j-rows) transposed into Bs[k][j]
        #pragma unroll
        for (int q = 0; q < 8; q++) {
            int id = q * 256 + t;
            int j  = id >> 4;
            int c  = (id & 15) * 4;
            float4 v = *(const float4*)(hn + (jt + j) * DIM + c);
            Bs[(c + 0) * 132 + j] = v.x;
            Bs[(c + 1) * 132 + j] = v.y;
            Bs[(c + 2) * 132 + j] = v.z;
            Bs[(c + 3) * 132 + j] = v.w;
        }
        __syncthreads();

        float acc[8][4];
        #pragma unroll
        for (int a = 0; a < 8; a++)
            #pragma unroll
            for (int b = 0; b < 4; b++) acc[a][b] = 0.0f;

        #pragma unroll 16
        for (int k = 0; k < 64; k++) {
            float4 b4 = *(const float4*)&Bs[k * 132 + j0];
            float4 a0 = *(const float4*)&As[k * 68 + i0];
            float4 a1 = *(const float4*)&As[k * 68 + i0 + 4];
            float av[8] = {a0.x, a0.y, a0.z, a0.w, a1.x, a1.y, a1.z, a1.w};
            #pragma unroll
            for (int a = 0; a < 8; a++) {
                acc[a][0] += av[a] * b4.x;
                acc[a][1] += av[a] * b4.y;
                acc[a][2] += av[a] * b4.z;
                acc[a][3] += av[a] * b4.w;
            }
        }

        // threshold + collect survivors
        #pragma unroll
        for (int a = 0; a < 8; a++) {
            #pragma unroll
            for (int b = 0; b < 4; b++) {
                float v = acc[a][b];
                if (v >= 0.5f) {
                    int r = i0 + a;
                    int p = atomicAdd(&cnt[r], 1);
                    if (p < CAP) {
                        keptV[r * CAP + p] = v;
                        keptJ[r * CAP + p] = jt + j0 + b;
                    }
                }
            }
        }
        __syncthreads();
    }

    // -------- per-row top-k (one warp per row, 8 rows each) --------
    int warp = t >> 5, lane = t & 31;
    for (int r = warp; r < BI; r += 8) {
        int m = cnt[r];
        if (m > CAP) m = CAP;
        float* kv = keptV + r * CAP;
        int*   kj = keptJ + r * CAP;
        int nsel = m < TOPK ? m : TOPK;

        // selection sort of survivors: (value desc, index asc) — matches JAX
        for (int s = 0; s < nsel; s++) {
            float bv = -1.0f; int bj = NN; int bp = -1;
            for (int p = lane; p < m; p += 32) {
                float v = kv[p]; int j = kj[p];
                if (v > bv || (v == bv && j < bj)) { bv = v; bj = j; bp = p; }
            }
            #pragma unroll
            for (int o = 16; o; o >>= 1) {
                float ov = __shfl_xor_sync(0xffffffffu, bv, o);
                int   oj = __shfl_xor_sync(0xffffffffu, bj, o);
                int   op = __shfl_xor_sync(0xffffffffu, bp, o);
                if (ov > bv || (ov == bv && oj < bj)) { bv = ov; bj = oj; bp = op; }
            }
            if (lane == 0) {
                H[s * NN + bj] = 1.0f;
                kv[bp] = -1.0f;           // mark used
            }
            __syncwarp();
        }

        // fill remaining slots with the zeros: ascending index, skipping
        // survivor indices (JAX stable tie-break among equal 0.0 values)
        if (lane == 0) {
            int s = nsel;
            int j = 0;
            while (s < TOPK) {
                bool kept = false;
                for (int p = 0; p < m; p++)
                    if (kj[p] == j) { kept = true; break; }
                if (!kept) { H[s * NN + j] = 1.0f; s++; }
                j++;
            }
        }
        __syncwarp();
    }
}

// ---------------------------------------------------------------------------
// launch
// ---------------------------------------------------------------------------
extern "C" void kernel_launch(void* const* d_in, const int* in_sizes, int n_in,
                              void* d_out, int out_size)
{
    const int* idx       = (const int*)d_in[0];
    const float* emb     = (const float*)d_in[1];
    const float* W       = (const float*)d_in[2];
    const float* bias    = (const float*)d_in[3];
    float* H             = (float*)d_out;

    const int smem_bytes = (64 * 68 + 64 * 132 + BI * CAP) * 4   // As + Bs + keptV
                         + BI * CAP * 4                           // keptJ
                         + BI * 4;                                // cnt
    cudaFuncSetAttribute(sim_topk_kernel,
                         cudaFuncAttributeMaxDynamicSharedMemorySize, smem_bytes);

    hn_kernel<<<NN / 4, NT>>>(idx, emb, W, bias, H);
    sim_topk_kernel<<<NN / BI, NT, smem_bytes>>>(H);
}

// round 3
// speedup vs baseline: 1.3525x; 1.3525x over previous
#include <cuda_runtime.h>
#include <cuda_bf16.h>
#include <math.h>

#define NN    8192
#define DIM   64
#define TOPK  64
#define BI    64      // i-rows per block (kernel 2)
#define TJ    128     // j-tile width
#define CAP   128     // max kept (sim>=0.5) entries per row
#define NT2   512

// hn transposed: hnT[d][row], 64 x 8192 fp32 = 2MB static scratch
__device__ float g_hnT[DIM * NN];

// ---------------------------------------------------------------------------
// Kernel 1: hn = normalize(tanh(3*(emb[idx] @ W^T + b))), stored TRANSPOSED
// into g_hnT[d*NN + row]. Also zeroes H (exact cover 2048*256 == 64*8192).
// idx is int32 on device (JAX x64-disabled).
// ---------------------------------------------------------------------------
__global__ void __launch_bounds__(256) hn_kernel(
    const int* __restrict__ idx,
    const float* __restrict__ emb,
    const float* __restrict__ W,
    const float* __restrict__ bias,
    float* __restrict__ H)
{
    __shared__ float Ws[64 * 65];   // W padded: row d at Ws[d*65 + k]
    __shared__ float xs[4][64];
    __shared__ float red[4][2];

    int t = threadIdx.x;

    // zero output H
    H[blockIdx.x * 256 + t] = 0.0f;

    // cooperative load of W into padded shared
    {
        int r  = t >> 2;
        int c0 = (t & 3) * 16;
        const float4* src = (const float4*)(W + r * 64 + c0);
        #pragma unroll
        for (int q = 0; q < 4; q++) {
            float4 v = src[q];
            int c = c0 + q * 4;
            Ws[r * 65 + c + 0] = v.x;
            Ws[r * 65 + c + 1] = v.y;
            Ws[r * 65 + c + 2] = v.z;
            Ws[r * 65 + c + 3] = v.w;
        }
    }

    int g   = t >> 6;        // row group 0..3
    int d   = t & 63;        // output dim
    int row = blockIdx.x * 4 + g;

    int src_row = idx[row] & (NN - 1);
    xs[g][d] = emb[src_row * DIM + d];
    __syncthreads();

    float s = bias[d];
    #pragma unroll
    for (int k = 0; k < 64; k++)
        s += xs[g][k] * Ws[d * 65 + k];

    float h  = tanhf(3.0f * s);
    float sq = h * h;
    #pragma unroll
    for (int o = 16; o; o >>= 1)
        sq += __shfl_xor_sync(0xffffffffu, sq, o);
    int wig = (t >> 5) & 1;
    if ((t & 31) == 0) red[g][wig] = sq;
    __syncthreads();

    float nrm = sqrtf(red[g][0] + red[g][1]);
    nrm = fmaxf(nrm, 1e-8f);
    g_hnT[d * NN + row] = h / nrm;   // transposed store
}

// ---------------------------------------------------------------------------
// Kernel 2: fused sim = hn@hn^T, threshold >= 0.5, collect survivors,
// exact top-64 with JAX stable tie-break, scatter into H.
// 512 threads (16 warps), 4x4 register tile, conflict-free smem access,
// no in-block transpose (hnT already K-major). grid 128, ~114KB smem.
// ---------------------------------------------------------------------------
extern __shared__ float smem2[];

__global__ void __launch_bounds__(512) sim_topk_kernel(float* __restrict__ H)
{
    const float* __restrict__ hnT = g_hnT;

    float* As    = smem2;                       // [64][68]  As[k][i]
    float* Bs    = As + 64 * 68;                // [64][132] Bs[k][j]
    float* keptV = Bs + 64 * 132;               // [BI*CAP]
    int*   keptJ = (int*)(keptV + BI * CAP);    // [BI*CAP]
    int*   cnt   = keptJ + BI * CAP;            // [BI]

    int t  = threadIdx.x;
    int ib = blockIdx.x * BI;

    if (t < BI) cnt[t] = 0;

    // load A tile: As[k][i] = hnT[k][ib+i]  (coalesced, no transpose)
    #pragma unroll
    for (int q = 0; q < 2; q++) {
        int id = q * 512 + t;
        int k  = id >> 4;
        int i4 = (id & 15) * 4;
        float4 v = *(const float4*)(hnT + k * NN + ib + i4);
        *(float4*)(As + k * 68 + i4) = v;
    }
    __syncthreads();

    int w  = t >> 5;          // warp 0..15 -> i group
    int l  = t & 31;          // lane       -> j group
    int i0 = w * 4;
    int j0 = l * 4;

    for (int jt = 0; jt < NN; jt += TJ) {
        // load B tile: Bs[k][j] = hnT[k][jt+j]  (coalesced, no transpose)
        #pragma unroll
        for (int q = 0; q < 4; q++) {
            int id = q * 512 + t;
            int k  = id >> 5;
            int j4 = (id & 31) * 4;
            float4 v = *(const float4*)(hnT + k * NN + jt + j4);
            *(float4*)(Bs + k * 132 + j4) = v;
        }
        __syncthreads();

        float acc[4][4];
        #pragma unroll
        for (int a = 0; a < 4; a++)
            #pragma unroll
            for (int b = 0; b < 4; b++) acc[a][b] = 0.0f;

        #pragma unroll 8
        for (int k = 0; k < 64; k++) {
            float4 a4 = *(const float4*)(As + k * 68 + i0);   // warp-broadcast
            float4 b4 = *(const float4*)(Bs + k * 132 + j0);  // conflict-free
            float av[4] = {a4.x, a4.y, a4.z, a4.w};
            float bv[4] = {b4.x, b4.y, b4.z, b4.w};
            #pragma unroll
            for (int a = 0; a < 4; a++) {
                acc[a][0] += av[a] * bv[0];
                acc[a][1] += av[a] * bv[1];
                acc[a][2] += av[a] * bv[2];
                acc[a][3] += av[a] * bv[3];
            }
        }

        // threshold + collect survivors
        #pragma unroll
        for (int a = 0; a < 4; a++) {
            #pragma unroll
            for (int b = 0; b < 4; b++) {
                float v = acc[a][b];
                if (v >= 0.5f) {
                    int r = i0 + a;
                    int p = atomicAdd(&cnt[r], 1);
                    if (p < CAP) {
                        keptV[r * CAP + p] = v;
                        keptJ[r * CAP + p] = jt + j0 + b;
                    }
                }
            }
        }
        __syncthreads();
    }

    // -------- per-row top-k (one warp per row, 16 warps over 64 rows) ------
    for (int r = w; r < BI; r += 16) {
        int m = cnt[r];
        if (m > CAP) m = CAP;
        float* kv = keptV + r * CAP;
        int*   kj = keptJ + r * CAP;
        int nsel = m < TOPK ? m : TOPK;

        // selection sort of survivors: (value desc, index asc) — matches JAX
        for (int s = 0; s < nsel; s++) {
            float bv = -1.0f; int bj = NN; int bp = -1;
            for (int p = l; p < m; p += 32) {
                float v = kv[p]; int j = kj[p];
                if (v > bv || (v == bv && j < bj)) { bv = v; bj = j; bp = p; }
            }
            #pragma unroll
            for (int o = 16; o; o >>= 1) {
                float ov = __shfl_xor_sync(0xffffffffu, bv, o);
                int   oj = __shfl_xor_sync(0xffffffffu, bj, o);
                int   op = __shfl_xor_sync(0xffffffffu, bp, o);
                if (ov > bv || (ov == bv && oj < bj)) { bv = ov; bj = oj; bp = op; }
            }
            if (l == 0) {
                H[s * NN + bj] = 1.0f;
                kv[bp] = -1.0f;
            }
            __syncwarp();
        }

        // fill remaining slots with zeros: ascending index, skipping survivors
        if (l == 0) {
            int s = nsel;
            int j = 0;
            while (s < TOPK) {
                bool kept = false;
                for (int p = 0; p < m; p++)
                    if (kj[p] == j) { kept = true; break; }
                if (!kept) { H[s * NN + j] = 1.0f; s++; }
                j++;
            }
        }
        __syncwarp();
    }
}

// ---------------------------------------------------------------------------
// launch
// ---------------------------------------------------------------------------
extern "C" void kernel_launch(void* const* d_in, const int* in_sizes, int n_in,
                              void* d_out, int out_size)
{
    const int* idx       = (const int*)d_in[0];
    const float* emb     = (const float*)d_in[1];
    const float* W       = (const float*)d_in[2];
    const float* bias    = (const float*)d_in[3];
    float* H             = (float*)d_out;

    const int smem_bytes = (64 * 68 + 64 * 132 + BI * CAP) * 4   // As + Bs + keptV
                         + BI * CAP * 4                           // keptJ
                         + BI * 4;                                // cnt
    cudaFuncSetAttribute(sim_topk_kernel,
                         cudaFuncAttributeMaxDynamicSharedMemorySize, smem_bytes);

    hn_kernel<<<NN / 4, 256>>>(idx, emb, W, bias, H);
    sim_topk_kernel<<<NN / BI, NT2, smem_bytes>>>(H);
}

// round 4
// speedup vs baseline: 2.6172x; 1.9351x over previous
#include <cuda_runtime.h>
#include <cuda_bf16.h>
#include <math.h>

#define NN    8192
#define DIM   64
#define TOPK  64
#define TS    128           // square tile size for symmetric GEMM
#define NTILE (NN / TS)     // 64
#define NJOBS (NTILE * (NTILE + 1) / 2)   // 2080
#define GCAP  128           // global survivor capacity per row

// scratch (static device globals; no allocs allowed)
__device__ float g_hnT[DIM * NN];        // hn transposed: hnT[d][row]
__device__ float g_keptV[NN * GCAP];     // survivor values per row
__device__ int   g_keptJ[NN * GCAP];     // survivor indices per row
__device__ int   g_cnt[NN];              // survivor counts per row

// ---------------------------------------------------------------------------
// Kernel 1: hn = normalize(tanh(3*(emb[idx] @ W^T + b))), stored transposed.
// Also zeroes H (exact cover) and g_cnt. idx is int32 (JAX x64-disabled).
// ---------------------------------------------------------------------------
__global__ void __launch_bounds__(256) hn_kernel(
    const int* __restrict__ idx,
    const float* __restrict__ emb,
    const float* __restrict__ W,
    const float* __restrict__ bias,
    float* __restrict__ H)
{
    __shared__ float Ws[64 * 65];
    __shared__ float xs[4][64];
    __shared__ float red[4][2];

    int t = threadIdx.x;

    H[blockIdx.x * 256 + t] = 0.0f;                 // zero output H
    if (blockIdx.x < 32) g_cnt[blockIdx.x * 256 + t] = 0;   // zero counts

    {   // W into padded shared
        int r  = t >> 2;
        int c0 = (t & 3) * 16;
        const float4* src = (const float4*)(W + r * 64 + c0);
        #pragma unroll
        for (int q = 0; q < 4; q++) {
            float4 v = src[q];
            int c = c0 + q * 4;
            Ws[r * 65 + c + 0] = v.x;
            Ws[r * 65 + c + 1] = v.y;
            Ws[r * 65 + c + 2] = v.z;
            Ws[r * 65 + c + 3] = v.w;
        }
    }

    int g   = t >> 6;
    int d   = t & 63;
    int row = blockIdx.x * 4 + g;

    int src_row = idx[row] & (NN - 1);
    xs[g][d] = emb[src_row * DIM + d];
    __syncthreads();

    float s = bias[d];
    #pragma unroll
    for (int k = 0; k < 64; k++)
        s += xs[g][k] * Ws[d * 65 + k];

    float h  = tanhf(3.0f * s);
    float sq = h * h;
    #pragma unroll
    for (int o = 16; o; o >>= 1)
        sq += __shfl_xor_sync(0xffffffffu, sq, o);
    int wig = (t >> 5) & 1;
    if ((t & 31) == 0) red[g][wig] = sq;
    __syncthreads();

    float nrm = fmaxf(sqrtf(red[g][0] + red[g][1]), 1e-8f);
    g_hnT[d * NN + row] = h / nrm;
}

// ---------------------------------------------------------------------------
// Kernel 2: symmetric tiled GEMM. One block per (ti<=tj) 128x128 tile pair.
// 256 threads, 8x8 register tile. Survivors (v>=0.5) pushed to global row
// lists of BOTH i and j (diagonal tile: j>=i only).
// ---------------------------------------------------------------------------
extern __shared__ float smem2[];

__device__ __forceinline__ void push_surv(int r, float v, int j)
{
    int p = atomicAdd(&g_cnt[r], 1);
    if (p < GCAP) {
        g_keptV[r * GCAP + p] = v;
        g_keptJ[r * GCAP + p] = j;
    }
}

__global__ void __launch_bounds__(256) sym_tile_kernel()
{
    const float* __restrict__ hnT = g_hnT;
    float* As = smem2;            // [64][128]  As[k][i]
    float* Bs = As + 64 * TS;     // [64][128]  Bs[k][j]

    // decode triangular job id -> (ti, tj), ti <= tj
    int b = blockIdx.x, ti = 0;
    while (b >= NTILE - ti) { b -= NTILE - ti; ti++; }
    int tj = ti + b;

    int t = threadIdx.x;

    // load A and B tiles (each 64k x 128, coalesced float4 from K-major hnT)
    #pragma unroll
    for (int q = 0; q < 8; q++) {
        int id = q * 256 + t;
        int k  = id >> 5;
        int c4 = (id & 31) * 4;
        *(float4*)(As + k * TS + c4) = *(const float4*)(hnT + k * NN + ti * TS + c4);
        *(float4*)(Bs + k * TS + c4) = *(const float4*)(hnT + k * NN + tj * TS + c4);
    }
    __syncthreads();

    int w    = t >> 5;           // warp 0..7
    int l    = t & 31;
    int wi   = w >> 1;           // 0..3
    int wj   = w & 1;            // 0..1
    int isub = l & 3;
    int jsub = l >> 2;
    int i0 = wi * 32 + isub * 8;
    int j0 = wj * 64 + jsub * 8;

    float acc[8][8];
    #pragma unroll
    for (int a = 0; a < 8; a++)
        #pragma unroll
        for (int c = 0; c < 8; c++) acc[a][c] = 0.0f;

    #pragma unroll 4
    for (int k = 0; k < 64; k++) {
        float4 a0 = *(const float4*)(As + k * TS + i0);
        float4 a1 = *(const float4*)(As + k * TS + i0 + 4);
        float4 b0 = *(const float4*)(Bs + k * TS + j0);
        float4 b1 = *(const float4*)(Bs + k * TS + j0 + 4);
        float av[8] = {a0.x, a0.y, a0.z, a0.w, a1.x, a1.y, a1.z, a1.w};
        float bv[8] = {b0.x, b0.y, b0.z, b0.w, b1.x, b1.y, b1.z, b1.w};
        #pragma unroll
        for (int a = 0; a < 8; a++)
            #pragma unroll
            for (int c = 0; c < 8; c++)
                acc[a][c] += av[a] * bv[c];
    }

    // threshold + symmetric survivor push
    bool diag = (ti == tj);
    #pragma unroll
    for (int a = 0; a < 8; a++) {
        int gi = ti * TS + i0 + a;
        #pragma unroll
        for (int c = 0; c < 8; c++) {
            float v = acc[a][c];
            if (v >= 0.5f) {
                int gj = tj * TS + j0 + c;
                if (!diag || gj > gi) {
                    push_surv(gi, v, gj);
                    push_surv(gj, v, gi);
                } else if (gj == gi) {
                    push_surv(gi, v, gi);
                }
            }
        }
    }
}

// ---------------------------------------------------------------------------
// Kernel 3: per-row top-64 with JAX stable tie-break from global survivor
// lists; scatter into H. One warp per row.
// ---------------------------------------------------------------------------
__global__ void __launch_bounds__(256) topk_kernel(float* __restrict__ H)
{
    int t = threadIdx.x;
    int w = t >> 5, l = t & 31;
    int row = blockIdx.x * 8 + w;

    int m = g_cnt[row];
    if (m > GCAP) m = GCAP;
    float* kv = g_keptV + row * GCAP;
    int*   kj = g_keptJ + row * GCAP;
    int nsel = m < TOPK ? m : TOPK;

    // selection sort of survivors: (value desc, index asc) — order-independent
    for (int s = 0; s < nsel; s++) {
        float bv = -1.0f; int bj = NN; int bp = -1;
        for (int p = l; p < m; p += 32) {
            float v = kv[p]; int j = kj[p];
            if (v > bv || (v == bv && j < bj)) { bv = v; bj = j; bp = p; }
        }
        #pragma unroll
        for (int o = 16; o; o >>= 1) {
            float ov = __shfl_xor_sync(0xffffffffu, bv, o);
            int   oj = __shfl_xor_sync(0xffffffffu, bj, o);
            int   op = __shfl_xor_sync(0xffffffffu, bp, o);
            if (ov > bv || (ov == bv && oj < bj)) { bv = ov; bj = oj; bp = op; }
        }
        if (l == 0) {
            H[s * NN + bj] = 1.0f;
            kv[bp] = -1.0f;
        }
        __syncwarp();
    }

    // fill remaining slots with zeros: ascending index, skipping survivors
    if (l == 0) {
        int s = nsel;
        int j = 0;
        while (s < TOPK) {
            bool kept = false;
            for (int p = 0; p < m; p++)
                if (kj[p] == j) { kept = true; break; }
            if (!kept) { H[s * NN + j] = 1.0f; s++; }
            j++;
        }
    }
}

// ---------------------------------------------------------------------------
// launch
// ---------------------------------------------------------------------------
extern "C" void kernel_launch(void* const* d_in, const int* in_sizes, int n_in,
                              void* d_out, int out_size)
{
    const int* idx    = (const int*)d_in[0];
    const float* emb  = (const float*)d_in[1];
    const float* W    = (const float*)d_in[2];
    const float* bias = (const float*)d_in[3];
    float* H          = (float*)d_out;

    const int smem_bytes = 2 * 64 * TS * 4;   // As + Bs = 64KB
    cudaFuncSetAttribute(sym_tile_kernel,
                         cudaFuncAttributeMaxDynamicSharedMemorySize, smem_bytes);

    hn_kernel<<<NN / 4, 256>>>(idx, emb, W, bias, H);
    sym_tile_kernel<<<NJOBS, 256, smem_bytes>>>();
    topk_kernel<<<NN / 8, 256>>>(H);
}

// round 6
// speedup vs baseline: 3.9882x; 1.5238x over previous
#include <cuda_runtime.h>
#include <cuda_bf16.h>
#include <math.h>
#include <stdint.h>

#define NN    8192
#define DIM   64
#define TOPK  64
#define CCAP  128
#define SCREEN 0.49f
#define TS    128
#define PAD   72            // bf16 row pitch in shared (144B, conflict-free ldmatrix)
#define NTILE (NN / TS)     // 64
#define NJOBS (NTILE * (NTILE + 1) / 2)   // 2080

// ---- static device scratch ----
__device__ float         g_hn[NN * DIM];      // fp32 hn row-major (exact recheck)
__device__ __nv_bfloat16 g_hnbf[NN * DIM];    // bf16 hn row-major (TC screen)
__device__ int           g_candJ[NN * CCAP];
__device__ int           g_ccnt[NN];

// ---------------------------------------------------------------------------
// helpers: baseline (non-'a') tensor core ops, valid on compute_100
// ---------------------------------------------------------------------------
__device__ __forceinline__ uint32_t smem_u32(const void* p) {
    uint32_t a;
    asm("{ .reg .u64 t; cvta.to.shared.u64 t, %1; cvt.u32.u64 %0, t; }"
        : "=r"(a) : "l"(p));
    return a;
}
__device__ __forceinline__ void ldsm4(uint32_t* r, uint32_t addr) {
    asm volatile("ldmatrix.sync.aligned.m8n8.x4.shared.b16 {%0,%1,%2,%3}, [%4];"
                 : "=r"(r[0]), "=r"(r[1]), "=r"(r[2]), "=r"(r[3]) : "r"(addr));
}
__device__ __forceinline__ void mma16816(float* c, const uint32_t* a, const uint32_t* b) {
    asm volatile(
        "mma.sync.aligned.m16n8k16.row.col.f32.bf16.bf16.f32 "
        "{%0,%1,%2,%3}, {%4,%5,%6,%7}, {%8,%9}, {%0,%1,%2,%3};"
        : "+f"(c[0]), "+f"(c[1]), "+f"(c[2]), "+f"(c[3])
        : "r"(a[0]), "r"(a[1]), "r"(a[2]), "r"(a[3]), "r"(b[0]), "r"(b[1]));
}

// ---------------------------------------------------------------------------
// Kernel 1: hn = normalize(tanh(3*(emb[idx]@W^T + b))), fp32 + bf16, row-major.
// 512 blocks x 16 rows: W loaded to shared ONCE per block (was per-4-rows).
// Also zeroes H and g_ccnt. idx is int32 (JAX x64-disabled).
// ---------------------------------------------------------------------------
__global__ void __launch_bounds__(256) hn_kernel(
    const int* __restrict__ idx,
    const float* __restrict__ emb,
    const float* __restrict__ W,
    const float* __restrict__ bias,
    float* __restrict__ H)
{
    __shared__ float WsT[64 * 68];   // WsT[k][d], pitch 68 (16B-aligned rows)
    __shared__ float xs[16][64];
    __shared__ int   s_src[16];
    __shared__ float s_bias[64];

    int t = threadIdx.x;

    // zero H (512*256 float4 == 64*8192 floats) and candidate counts
    ((float4*)H)[blockIdx.x * 256 + t] = make_float4(0.f, 0.f, 0.f, 0.f);
    if (blockIdx.x < 8)
        ((int4*)g_ccnt)[blockIdx.x * 256 + t] = make_int4(0, 0, 0, 0);

    if (t < 16) s_src[t] = idx[blockIdx.x * 16 + t] & (NN - 1);
    if (t < 64) s_bias[t] = bias[t];

    // W[d][k] -> WsT[k][d]
    #pragma unroll
    for (int q = 0; q < 16; q++) {
        int e = q * 256 + t;
        WsT[(e & 63) * 68 + (e >> 6)] = W[e];
    }
    __syncthreads();

    #pragma unroll
    for (int q = 0; q < 4; q++) {
        int e = q * 256 + t;
        int r = e >> 6, k = e & 63;
        xs[r][k] = emb[s_src[r] * DIM + k];
    }
    __syncthreads();

    int r  = t >> 4;          // local row 0..15
    int d0 = (t & 15) * 4;    // this thread's 4 output dims

    float a0 = s_bias[d0], a1 = s_bias[d0 + 1], a2 = s_bias[d0 + 2], a3 = s_bias[d0 + 3];
    #pragma unroll
    for (int k = 0; k < 64; k++) {
        float  xv = xs[r][k];
        float4 w4 = *(const float4*)&WsT[k * 68 + d0];
        a0 += xv * w4.x; a1 += xv * w4.y; a2 += xv * w4.z; a3 += xv * w4.w;
    }

    float h0 = tanhf(3.0f * a0), h1 = tanhf(3.0f * a1);
    float h2 = tanhf(3.0f * a2), h3 = tanhf(3.0f * a3);

    float sq = h0 * h0 + h1 * h1 + h2 * h2 + h3 * h3;
    #pragma unroll
    for (int o = 8; o; o >>= 1)
        sq += __shfl_xor_sync(0xffffffffu, sq, o);   // reduce over 16-thread group

    float nrm = fmaxf(sqrtf(sq), 1e-8f);
    float v0 = h0 / nrm, v1 = h1 / nrm, v2 = h2 / nrm, v3 = h3 / nrm;

    int row = blockIdx.x * 16 + r;
    *(float4*)&g_hn[row * DIM + d0] = make_float4(v0, v1, v2, v3);

    __nv_bfloat162* bp = (__nv_bfloat162*)&g_hnbf[row * DIM + d0];
    bp[0] = __nv_bfloat162(__float2bfloat16(v0), __float2bfloat16(v1));
    bp[1] = __nv_bfloat162(__float2bfloat16(v2), __float2bfloat16(v3));
}

// ---------------------------------------------------------------------------
// Kernel 2: bf16 HMMA screen, symmetric triangular 128x128 tiles (2080 blocks).
// 8 warps, each 64x32 via m16n8k16. sim_bf16 >= 0.49 -> push candidate indices
// to both rows' lists (diagonal: j>=i).
// ---------------------------------------------------------------------------
__device__ __forceinline__ void screen_push(int gi, int gj, float v, bool diag)
{
    if (v >= SCREEN) {
        if (!diag || gj > gi) {
            int p = atomicAdd(&g_ccnt[gi], 1);
            if (p < CCAP) g_candJ[gi * CCAP + p] = gj;
            p = atomicAdd(&g_ccnt[gj], 1);
            if (p < CCAP) g_candJ[gj * CCAP + p] = gi;
        } else if (gj == gi) {
            int p = atomicAdd(&g_ccnt[gi], 1);
            if (p < CCAP) g_candJ[gi * CCAP + p] = gi;
        }
    }
}

__global__ void __launch_bounds__(256) sim_mma_kernel()
{
    __shared__ __nv_bfloat16 sA[TS * PAD];
    __shared__ __nv_bfloat16 sB[TS * PAD];

    // triangular job -> (ti, tj), ti <= tj
    int b = blockIdx.x, ti = 0;
    while (b >= NTILE - ti) { b -= NTILE - ti; ti++; }
    int tj = ti + b;
    int ib = ti * TS, jb = tj * TS;

    int t = threadIdx.x, wid = t >> 5, l = t & 31;

    const __nv_bfloat16* hb = g_hnbf;
    #pragma unroll
    for (int q = 0; q < 4; q++) {
        int id  = q * 256 + t;
        int row = id >> 3, c8 = (id & 7) * 8;
        *(uint4*)(sA + row * PAD + c8) = *(const uint4*)(hb + (ib + row) * DIM + c8);
        *(uint4*)(sB + row * PAD + c8) = *(const uint4*)(hb + (jb + row) * DIM + c8);
    }
    __syncthreads();

    int wr = wid >> 2, wc = wid & 3;
    int R0 = wr * 64, C0 = wc * 32;

    float acc[4][4][4];
    #pragma unroll
    for (int mt = 0; mt < 4; mt++)
        #pragma unroll
        for (int nt = 0; nt < 4; nt++)
            #pragma unroll
            for (int e = 0; e < 4; e++) acc[mt][nt][e] = 0.0f;

    uint32_t aBase = smem_u32(sA);
    uint32_t bBase = smem_u32(sB);

    int lr    = l & 7;
    int khalf = (l >> 3) & 1;
    int kq    = l >> 4;

    #pragma unroll
    for (int ks = 0; ks < 4; ks++) {
        int k0 = ks * 16;

        uint32_t af[4][4];
        #pragma unroll
        for (int mt = 0; mt < 4; mt++) {
            // lanes 0-7: rows 0-7 k0-7 | 8-15: rows 8-15 k0-7 | 16-23: rows 0-7 k8-15 | 24-31: rows 8-15 k8-15
            uint32_t addr = aBase +
                (uint32_t)(((R0 + mt * 16 + lr + khalf * 8) * PAD + k0 + kq * 8) * 2);
            ldsm4(af[mt], addr);
        }

        uint32_t bf[4][2];
        #pragma unroll
        for (int np = 0; np < 2; np++) {
            // lanes 0-7: nt(np*2) k0-7 | 8-15: nt(np*2) k8-15 | 16-23: nt(np*2+1) k0-7 | 24-31: +k8-15
            uint32_t r4[4];
            uint32_t addr = bBase +
                (uint32_t)(((C0 + np * 16 + kq * 8 + lr) * PAD + k0 + khalf * 8) * 2);
            ldsm4(r4, addr);
            bf[np * 2 + 0][0] = r4[0]; bf[np * 2 + 0][1] = r4[1];
            bf[np * 2 + 1][0] = r4[2]; bf[np * 2 + 1][1] = r4[3];
        }

        #pragma unroll
        for (int mt = 0; mt < 4; mt++)
            #pragma unroll
            for (int nt = 0; nt < 4; nt++)
                mma16816(acc[mt][nt], af[mt], bf[nt]);
    }

    // epilogue: c0:(r,c) c1:(r,c+1) c2:(r+8,c) c3:(r+8,c+1); r=l>>2, c=2*(l&3)
    bool diag = (ti == tj);
    int gr = l >> 2, tg = l & 3;
    #pragma unroll
    for (int mt = 0; mt < 4; mt++) {
        int gi0 = ib + R0 + mt * 16 + gr;
        #pragma unroll
        for (int nt = 0; nt < 4; nt++) {
            int gj0 = jb + C0 + nt * 8 + tg * 2;
            float* c = acc[mt][nt];
            screen_push(gi0,     gj0,     c[0], diag);
            screen_push(gi0,     gj0 + 1, c[1], diag);
            screen_push(gi0 + 8, gj0,     c[2], diag);
            screen_push(gi0 + 8, gj0 + 1, c[3], diag);
        }
    }
}

// ---------------------------------------------------------------------------
// Kernel 3: exact fp32 recheck + per-row top-64 (JAX stable tie-break).
// One warp per row.
// ---------------------------------------------------------------------------
__global__ void __launch_bounds__(256) topk_kernel(float* __restrict__ H)
{
    __shared__ float sV[8][CCAP];
    __shared__ int   sJ[8][CCAP];

    int t = threadIdx.x, w = t >> 5, l = t & 31;
    int r = blockIdx.x * 8 + w;
    const float* __restrict__ hn = g_hn;

    int m = g_ccnt[r];
    if (m > CCAP) m = CCAP;

    float a1 = hn[r * DIM + l];
    float a2 = hn[r * DIM + 32 + l];

    int cnt = 0;
    for (int p = 0; p < m; p++) {
        int j = g_candJ[r * CCAP + p];
        float s = a1 * hn[j * DIM + l] + a2 * hn[j * DIM + 32 + l];
        #pragma unroll
        for (int o = 16; o; o >>= 1)
            s += __shfl_xor_sync(0xffffffffu, s, o);
        if (s >= 0.5f) {
            if (l == 0) { sV[w][cnt] = s; sJ[w][cnt] = j; }
            cnt++;
        }
    }
    __syncwarp();

    float* kv = sV[w];
    int*   kj = sJ[w];
    int nsel = cnt < TOPK ? cnt : TOPK;

    // selection: (value desc, index asc) — matches JAX top_k
    for (int s = 0; s < nsel; s++) {
        float bv = -1.0f; int bj = NN; int bp = -1;
        for (int p = l; p < cnt; p += 32) {
            float v = kv[p]; int j = kj[p];
            if (v > bv || (v == bv && j < bj)) { bv = v; bj = j; bp = p; }
        }
        #pragma unroll
        for (int o = 16; o; o >>= 1) {
            float ov = __shfl_xor_sync(0xffffffffu, bv, o);
            int   oj = __shfl_xor_sync(0xffffffffu, bj, o);
            int   op = __shfl_xor_sync(0xffffffffu, bp, o);
            if (ov > bv || (ov == bv && oj < bj)) { bv = ov; bj = oj; bp = op; }
        }
        if (l == 0) {
            H[s * NN + bj] = 1.0f;
            kv[bp] = -1.0f;
        }
        __syncwarp();
    }

    // fill remaining slots with zeros: ascending index, skipping survivors
    if (l == 0) {
        int s = nsel;
        int j = 0;
        while (s < TOPK) {
            bool kept = false;
            for (int p = 0; p < cnt; p++)
                if (kj[p] == j) { kept = true; break; }
            if (!kept) { H[s * NN + j] = 1.0f; s++; }
            j++;
        }
    }
}

// ---------------------------------------------------------------------------
// launch
// ---------------------------------------------------------------------------
extern "C" void kernel_launch(void* const* d_in, const int* in_sizes, int n_in,
                              void* d_out, int out_size)
{
    const int* idx    = (const int*)d_in[0];
    const float* emb  = (const float*)d_in[1];
    const float* W    = (const float*)d_in[2];
    const float* bias = (const float*)d_in[3];
    float* H          = (float*)d_out;

    hn_kernel<<<NN / 16, 256>>>(idx, emb, W, bias, H);
    sim_mma_kernel<<<NJOBS, 256>>>();
    topk_kernel<<<NN / 8, 256>>>(H);
}